// round 13
// baseline (speedup 1.0000x reference)
#include <cuda_runtime.h>
#include <cstdint>
#include <math.h>

#define B_   64
#define S_   1024
#define I_   256
#define H_   512
#define O_   512
#define G3H  1536

#define GR    96     // 3 groups x 32 CTAs, all resident (1 CTA/SM via smem)
#define RT    256    // 8 warps -> 2 per SMSP
#define STEPS 1026

typedef unsigned long long u64;

// ---------------------------------------------------------------------------
// Device-global scratch
// ---------------------------------------------------------------------------
__device__ float    g_gi0  [(size_t)S_ * G3H * B_];   // gi0 [t][row][b]
__device__ float    g_gi1  [2 * G3H * B_];            // gi1 ring [slot][row][b]
__device__ float    g_h1sq [(size_t)S_ * H_ * B_];    // hseq1 transposed [t][j][b]
__device__ float    g_h0T  [2 * H_ * B_];             // h0 double buffer [slot][j][b]
__device__ float    g_h1T  [2 * H_ * B_];             // h1 double buffer [slot][j][b]
__device__ unsigned g_sync [512];                     // [g*32] grp ctr, [400] root, [416] release

// ---------------------------------------------------------------------------
// f32x2 + cp.async helpers
// ---------------------------------------------------------------------------
__device__ __forceinline__ u64 pk2(float x) {
    u64 r; asm("mov.b64 %0, {%1, %1};" : "=l"(r) : "r"(__float_as_uint(x))); return r;
}
__device__ __forceinline__ void fma2(u64& d, u64 a, u64 b) {
    asm("fma.rn.f32x2 %0, %1, %2, %0;" : "+l"(d) : "l"(a), "l"(b));
}
__device__ __forceinline__ float2 up2(u64 u) {
    unsigned lo, hi; asm("mov.b64 {%0, %1}, %2;" : "=r"(lo), "=r"(hi) : "l"(u));
    return make_float2(__uint_as_float(lo), __uint_as_float(hi));
}
__device__ __forceinline__ void cpa16(float* smem, const float* g) {
    unsigned s = (unsigned)__cvta_generic_to_shared(smem);
    asm volatile("cp.async.cg.shared.global [%0], [%1], 16;" :: "r"(s), "l"(g));
}
__device__ __forceinline__ float sigmoidf_(float x) { return 1.f / (1.f + expf(-x)); }

// ---------------------------------------------------------------------------
// SGEMM + bias (unchanged from R11 — verified DRAM fix).
// MODE 0: A = x [B][S][I], M ordered m = t*64+b -> out gi[t][n][b], b-contig stores.
// MODE 3: A = h1sq [t][k][b] (rows m = t*64+b)  -> out[b][t][n].
// ---------------------------------------------------------------------------
template <int MODE>
__global__ void __launch_bounds__(256)
sgemm_bias(const float* __restrict__ A, const float* __restrict__ Bw,
           const float* __restrict__ bias, float* __restrict__ out,
           int M, int N, int K)
{
    __shared__ float As[16][132];
    __shared__ float Bs[16][68];

    const int tid = threadIdx.x;
    const int m0  = blockIdx.y * 128;
    const int n0  = blockIdx.x * 64;
    const int tx  = tid & 15;
    const int ty  = tid >> 4;

    const float* Bb = Bw + (size_t)n0 * K;

    u64 acc[4][4];
#pragma unroll
    for (int i = 0; i < 4; i++)
#pragma unroll
        for (int j = 0; j < 4; j++) acc[i][j] = 0ull;

    const int lr = tid >> 2;
    const int lk = (tid & 3) * 4;
    const int t0 = m0 >> 6;
    const int kk = tid >> 4, qq = tid & 15;

    for (int kt = 0; kt < K; kt += 16) {
        if (MODE == 0) {
#pragma unroll
            for (int p = 0; p < 2; p++) {
                const int r = lr + p * 64;
                float4 v = *(const float4*)&A[((size_t)(r & 63) * S_ + t0 + (r >> 6)) * I_ + kt + lk];
                As[lk + 0][r] = v.x;
                As[lk + 1][r] = v.y;
                As[lk + 2][r] = v.z;
                As[lk + 3][r] = v.w;
            }
        } else {
            float4 v0 = *(const float4*)&A[(((size_t)t0       * 512) + kt + kk) * 64 + qq * 4];
            float4 v1 = *(const float4*)&A[(((size_t)(t0 + 1) * 512) + kt + kk) * 64 + qq * 4];
            *(float4*)&As[kk][qq * 4]      = v0;
            *(float4*)&As[kk][64 + qq * 4] = v1;
        }
        {
            float4 v = *(const float4*)&Bb[(size_t)lr * K + kt + lk];
            Bs[lk + 0][lr] = v.x;
            Bs[lk + 1][lr] = v.y;
            Bs[lk + 2][lr] = v.z;
            Bs[lk + 3][lr] = v.w;
        }
        __syncthreads();

#pragma unroll
        for (int k = 0; k < 16; k++) {
            float4 bv = *(const float4*)&Bs[k][tx * 4];
            u64 bp0 = pk2(bv.x), bp1 = pk2(bv.y), bp2 = pk2(bv.z), bp3 = pk2(bv.w);
            ulonglong2 a01 = *(const ulonglong2*)&As[k][ty * 8];
            ulonglong2 a23 = *(const ulonglong2*)&As[k][ty * 8 + 4];
            u64 ap[4] = {a01.x, a01.y, a23.x, a23.y};
#pragma unroll
            for (int i = 0; i < 4; i++) {
                fma2(acc[i][0], ap[i], bp0);
                fma2(acc[i][1], ap[i], bp1);
                fma2(acc[i][2], ap[i], bp2);
                fma2(acc[i][3], ap[i], bp3);
            }
        }
        __syncthreads();
    }

    float bv[4];
    *(float4*)bv = *(const float4*)&bias[n0 + tx * 4];

    if (MODE == 0) {
        const int t  = t0 + (ty >> 3);
        const int b0 = (ty & 7) * 8;
#pragma unroll
        for (int j = 0; j < 4; j++) {
            const int n = n0 + tx * 4 + j;
            float2 p0 = up2(acc[0][j]), p1 = up2(acc[1][j]);
            float2 p2 = up2(acc[2][j]), p3 = up2(acc[3][j]);
            float4 w0, w1;
            w0.x = p0.x + bv[j]; w0.y = p0.y + bv[j];
            w0.z = p1.x + bv[j]; w0.w = p1.y + bv[j];
            w1.x = p2.x + bv[j]; w1.y = p2.y + bv[j];
            w1.z = p3.x + bv[j]; w1.w = p3.y + bv[j];
            float* q = out + ((size_t)t * G3H + n) * B_ + b0;
            *(float4*)&q[0] = w0;
            *(float4*)&q[4] = w1;
        }
    } else {
        float accf[8][4];
#pragma unroll
        for (int i = 0; i < 4; i++)
#pragma unroll
            for (int j = 0; j < 4; j++) {
                float2 v = up2(acc[i][j]);
                accf[2 * i + 0][j] = v.x;
                accf[2 * i + 1][j] = v.y;
            }
#pragma unroll
        for (int i = 0; i < 8; i++) {
            int m = m0 + ty * 8 + i;
            int t = m >> 6, b = m & 63;
            float4 c;
            c.x = accf[i][0] + bv[0];
            c.y = accf[i][1] + bv[1];
            c.z = accf[i][2] + bv[2];
            c.w = accf[i][3] + bv[3];
            *(float4*)&out[((size_t)b * S_ + t) * O_ + n0 + tx * 4] = c;
        }
    }
}

// ---------------------------------------------------------------------------
// Fused two-layer GRU wavefront. 96 CTAs = 3 groups x 32 (16 j each), RT=256.
//  G0: h0[s] = cell(h0[s-1], gi0[s]);  G1: gi1[s-1] = h0[s-1]@W_ih1^T + b;
//  G2: h1[s-2] = cell(h1[s-3], gi1[s-2]).
// NEW mapping: warp = (jq 0..3, bh 0..1) covers 4 j x 32 b; lane = (jl2, bs2).
//   -> h LDS = 1 wavefront/k/warp; weight LDS = 1 wf each.
// Weights PRE-DUPLICATED as (w,w) u64 pairs, packed per 2k:
//   WrzDup[k2][jl][2] ulonglong2 (128 KB), Wn2[k2][jl] float2 (32 KB).
//   -> r/z gates consume weights with ZERO MOVs; only 2 pk2 per k2 remain.
// h streamed via 2 x 32 KB double buffer (4 chunks of 128 k).
// smem: hs 65536 B @0 | WrzDup 131072 B @65536 | Wn2 32768 B @196608  = 224 KB
// ---------------------------------------------------------------------------
#define FUS_SMEM_BYTES 229376

__device__ __forceinline__ void compute_chunk(const float* __restrict__ hbuf,
                                              const ulonglong2* __restrict__ WrzD,
                                              const float2* __restrict__ Wn2,
                                              int jl, int bA, int k2base,
                                              u64* aR, u64* aZ, u64* aN)
{
#pragma unroll 8
    for (int i = 0; i < 64; i++) {
        const int k2 = k2base + i;
        const int kl = i * 2;
        ulonglong2 wa = WrzD[(k2 * 16 + jl) * 2 + 0];   // ((wr0,wr0),(wz0,wz0))
        ulonglong2 wb = WrzD[(k2 * 16 + jl) * 2 + 1];   // ((wr1,wr1),(wz1,wz1))
        float2 wn = Wn2[k2 * 16 + jl];
        u64 wn0 = pk2(wn.x), wn1 = pk2(wn.y);
        ulonglong2 h0 = *(const ulonglong2*)&hbuf[kl * 64 + bA];
        ulonglong2 h1 = *(const ulonglong2*)&hbuf[(kl + 1) * 64 + bA];
        fma2(aR[0], h0.x, wa.x); fma2(aR[1], h0.y, wa.x);
        fma2(aZ[0], h0.x, wa.y); fma2(aZ[1], h0.y, wa.y);
        fma2(aN[0], h0.x, wn0);  fma2(aN[1], h0.y, wn0);
        fma2(aR[0], h1.x, wb.x); fma2(aR[1], h1.y, wb.x);
        fma2(aZ[0], h1.x, wb.y); fma2(aZ[1], h1.y, wb.y);
        fma2(aN[0], h1.x, wn1);  fma2(aN[1], h1.y, wn1);
    }
}

__device__ __forceinline__ void chunk_issue(float* hb, const float* hsrc,
                                            int c, int tid)
{
    const float* s4 = hsrc + c * 8192;          // 32 KB chunk (128 k)
    float*       d4 = hb + (c & 1) * 8192;
#pragma unroll
    for (int u = 0; u < 8; u++)
        cpa16(d4 + (tid + u * RT) * 4, s4 + (tid + u * RT) * 4);
    asm volatile("cp.async.commit_group;");
}

__global__ void __launch_bounds__(RT, 1)
gru_fused(const float* __restrict__ gi0,
          const float* __restrict__ Whh0, const float* __restrict__ bhh0,
          const float* __restrict__ Wih1, const float* __restrict__ bih1,
          const float* __restrict__ Whh1, const float* __restrict__ bhh1,
          float* __restrict__ hid)    // [2][B][H] tail of d_out
{
    extern __shared__ float sm[];
    float*      hb   = sm;                                   // 65536 B
    ulonglong2* WrzD = (ulonglong2*)((char*)sm + 65536);     // 131072 B
    float2*     Wn2  = (float2*)((char*)sm + 196608);        // 32768 B

    const int tid   = threadIdx.x;
    const int cta   = blockIdx.x;
    const int grp   = cta >> 5;
    const int lc    = cta & 31;
    const int jbase = lc * 16;

    const float* Wsrc = (grp == 0) ? Whh0 : (grp == 1) ? Wih1 : Whh1;

    // Duplicated-pair weight preload: 16 j x 512 k x 3 gates.
    for (int i = tid; i < 16 * 512; i += RT) {
        int k = i & 511, jj = i >> 9;
        int j = jbase + jj;
        float wr = Wsrc[(size_t)j          * 512 + k];
        float wz = Wsrc[(size_t)(512 + j)  * 512 + k];
        float wn = Wsrc[(size_t)(1024 + j) * 512 + k];
        WrzD[(((k >> 1) * 16 + jj) * 2) + (k & 1)] =
            make_ulonglong2(pk2(wr), pk2(wz));
        ((float*)Wn2)[(((k >> 1) * 16 + jj) * 2) + (k & 1)] = wn;
    }

    // Mapping: warp = (jq, bh); lane = (jl2, bs2)
    const int w    = tid >> 5;
    const int lane = tid & 31;
    const int jq   = w & 3;
    const int bh   = w >> 2;            // 0..1
    const int jl2  = lane >> 3;         // 0..3
    const int bs2  = lane & 7;          // 0..7
    const int jl   = jq * 4 + jl2;      // 0..15
    const int bA   = bh * 32 + bs2 * 4; // 4 batch per thread
    const int j    = jbase + jl;

    float br = 0.f, bz = 0.f, bn = 0.f;
    if (grp == 0) { br = bhh0[j]; bz = bhh0[512 + j]; bn = bhh0[1024 + j]; }
    if (grp == 1) { br = bih1[j]; bz = bih1[512 + j]; bn = bih1[1024 + j]; }
    if (grp == 2) { br = bhh1[j]; bz = bhh1[512 + j]; bn = bhh1[1024 + j]; }

    __syncthreads();

    for (int s = 0; s < STEPS; s++) {
        const bool active = (grp == 0) ? (s < 1024)
                          : (grp == 1) ? (s >= 1 && s < 1025)
                                       : (s >= 2);
        if (active) {
            const float* hsrc = ((grp == 2) ? g_h1T : g_h0T)
                              + (((grp == 2 ? s - 2 : s) + 1) & 1) * (H_ * B_);

            chunk_issue(hb, hsrc, 0, tid);
            chunk_issue(hb, hsrc, 1, tid);

            // Prefetch gi + h_old via LDG (lands under the mainloop)
            float GIR[4], GIZ[4], GIN[4], hold[4];
            if (grp != 1) {
                const float* p = (grp == 0)
                    ? gi0   + (size_t)s * (G3H * 64)
                    : g_gi1 + (size_t)(s & 1) * (G3H * 64);
                *(float4*)&GIR[0]  = *(const float4*)&p[(size_t)j          * 64 + bA];
                *(float4*)&GIZ[0]  = *(const float4*)&p[(size_t)(512 + j)  * 64 + bA];
                *(float4*)&GIN[0]  = *(const float4*)&p[(size_t)(1024 + j) * 64 + bA];
                *(float4*)&hold[0] = *(const float4*)&hsrc[j * 64 + bA];
            }

            u64 aR[2] = {0,0}, aZ[2] = {0,0}, aN[2] = {0,0};

            asm volatile("cp.async.wait_group 1;");
            __syncthreads();
            compute_chunk(hb,        WrzD, Wn2, jl, bA, 0,   aR, aZ, aN);
            __syncthreads();
            chunk_issue(hb, hsrc, 2, tid);
            asm volatile("cp.async.wait_group 1;");
            __syncthreads();
            compute_chunk(hb + 8192, WrzD, Wn2, jl, bA, 64,  aR, aZ, aN);
            __syncthreads();
            chunk_issue(hb, hsrc, 3, tid);
            asm volatile("cp.async.wait_group 1;");
            __syncthreads();
            compute_chunk(hb,        WrzD, Wn2, jl, bA, 128, aR, aZ, aN);
            asm volatile("cp.async.wait_group 0;");
            __syncthreads();
            compute_chunk(hb + 8192, WrzD, Wn2, jl, bA, 192, aR, aZ, aN);

            float R[4], Z[4], N[4];
#pragma unroll
            for (int p = 0; p < 2; p++) {
                float2 r = up2(aR[p]), z = up2(aZ[p]), n = up2(aN[p]);
                R[2*p] = r.x; R[2*p+1] = r.y;
                Z[2*p] = z.x; Z[2*p+1] = z.y;
                N[2*p] = n.x; N[2*p+1] = n.y;
            }

            if (grp == 1) {
                float* q = g_gi1 + (size_t)((s - 1) & 1) * (G3H * 64);
                float o[4];
#pragma unroll
                for (int i = 0; i < 4; i++) o[i] = R[i] + br;
                *(float4*)&q[(size_t)j * 64 + bA] = *(float4*)&o[0];
#pragma unroll
                for (int i = 0; i < 4; i++) o[i] = Z[i] + bz;
                *(float4*)&q[(size_t)(512 + j) * 64 + bA] = *(float4*)&o[0];
#pragma unroll
                for (int i = 0; i < 4; i++) o[i] = N[i] + bn;
                *(float4*)&q[(size_t)(1024 + j) * 64 + bA] = *(float4*)&o[0];
            } else {
                float hn[4];
#pragma unroll
                for (int i = 0; i < 4; i++) {
                    float r_ = sigmoidf_(GIR[i] + R[i] + br);
                    float z_ = sigmoidf_(GIZ[i] + Z[i] + bz);
                    float n_ = tanhf(GIN[i] + r_ * (N[i] + bn));
                    hn[i] = (1.f - z_) * n_ + z_ * hold[i];
                }

                const int tau = (grp == 2) ? s - 2 : s;
                float* hdT = ((grp == 2) ? g_h1T : g_h0T) + (tau & 1) * (H_ * B_);
                *(float4*)&hdT[j * 64 + bA] = *(float4*)&hn[0];

                if (grp == 2) {
                    float* hq = g_h1sq + (size_t)tau * (H_ * B_);
                    *(float4*)&hq[j * 64 + bA] = *(float4*)&hn[0];
                }
                if (tau == S_ - 1) {
                    float* hd = hid + (grp == 2 ? B_ * H_ : 0);
#pragma unroll
                    for (int i = 0; i < 4; i++)
                        hd[(size_t)(bA + i) * H_ + j] = hn[i];
                }
            }
        }

        // ---- two-level grid barrier (unchanged, known-good) ----
        __syncthreads();
        if (tid == 0) {
            __threadfence();
            unsigned go = atomicAdd(&g_sync[(cta >> 3) * 32], 1u);
            if (go == (unsigned)(s + 1) * 8 - 1) {
                unsigned ro = atomicAdd(&g_sync[400], 1u);
                if (ro == (unsigned)(s + 1) * 12 - 1) {
                    __threadfence();
                    *((volatile unsigned*)&g_sync[416]) = (unsigned)(s + 1);
                }
            }
            while (*((volatile unsigned*)&g_sync[416]) < (unsigned)(s + 1)) { }
            __threadfence();
        }
        __syncthreads();
    }
}

// ---------------------------------------------------------------------------
// Launch
// ---------------------------------------------------------------------------
extern "C" void kernel_launch(void* const* d_in, const int* in_sizes, int n_in,
                              void* d_out, int out_size)
{
    const float* x    = (const float*)d_in[0];
    const float* Wih0 = (const float*)d_in[1];
    const float* Whh0 = (const float*)d_in[2];
    const float* bih0 = (const float*)d_in[3];
    const float* bhh0 = (const float*)d_in[4];
    const float* Wih1 = (const float*)d_in[5];
    const float* Whh1 = (const float*)d_in[6];
    const float* bih1 = (const float*)d_in[7];
    const float* bhh1 = (const float*)d_in[8];
    const float* Wfc  = (const float*)d_in[9];
    const float* bfc  = (const float*)d_in[10];

    float* out = (float*)d_out;                    // logits [B][S][O]
    float* hid = out + (size_t)B_ * S_ * O_;       // hidden [2][B][H]

    float *gi0, *h1sq, *h0T, *h1T;
    unsigned* sy;
    cudaGetSymbolAddress((void**)&gi0,  g_gi0);
    cudaGetSymbolAddress((void**)&h1sq, g_h1sq);
    cudaGetSymbolAddress((void**)&h0T,  g_h0T);
    cudaGetSymbolAddress((void**)&h1T,  g_h1T);
    cudaGetSymbolAddress((void**)&sy,   g_sync);

    cudaFuncSetAttribute(gru_fused, cudaFuncAttributeMaxDynamicSharedMemorySize,
                         FUS_SMEM_BYTES);

    const int M = B_ * S_;
    dim3 blk(256);
    dim3 gGI(G3H / 64, M / 128);   // 24 x 512
    dim3 gFC(O_ / 64, M / 128);    //  8 x 512

    // gi0 = x @ W_ih0^T + b_ih0   -> [t][row][b]  (coalesced b-axis stores)
    sgemm_bias<0><<<gGI, blk>>>(x, Wih0, bih0, gi0, M, G3H, I_);

    cudaMemsetAsync(h0T, 0, (size_t)2 * H_ * B_ * sizeof(float));
    cudaMemsetAsync(h1T, 0, (size_t)2 * H_ * B_ * sizeof(float));
    cudaMemsetAsync(sy, 0, 512 * sizeof(unsigned));

    gru_fused<<<GR, RT, FUS_SMEM_BYTES>>>(gi0, Whh0, bhh0, Wih1, bih1,
                                          Whh1, bhh1, hid);

    // logits = hseq1 @ W_fc^T + b_fc   (A read from transposed [t][j][b])
    sgemm_bias<3><<<gFC, blk>>>(h1sq, Wfc, bfc, out, M, O_, H_);
}

// round 15
// speedup vs baseline: 1.4431x; 1.4431x over previous
#include <cuda_runtime.h>
#include <cstdint>
#include <math.h>

#define B_   64
#define S_   1024
#define I_   256
#define H_   512
#define O_   512
#define G3H  1536

#define GR    96     // 3 groups x 32 CTAs, all resident (1 CTA/SM via smem)
#define RT    256    // 8 warps -> 2 per SMSP
#define STEPS 1026

typedef unsigned long long u64;

// ---------------------------------------------------------------------------
// Device-global scratch
// ---------------------------------------------------------------------------
__device__ float    g_gi0  [(size_t)S_ * G3H * B_];   // gi0 [t][row][b]
__device__ float    g_gi1  [2 * G3H * B_];            // gi1 ring [slot][row][b]
__device__ float    g_h1sq [(size_t)S_ * H_ * B_];    // hseq1 transposed [t][j][b]
__device__ float    g_h0T  [2 * H_ * B_];             // h0 double buffer [slot][j][b]
__device__ float    g_h1T  [2 * H_ * B_];             // h1 double buffer [slot][j][b]
__device__ unsigned g_sync [512];                     // [g*32] grp ctr, [400] root, [416] release

// ---------------------------------------------------------------------------
// f32x2 + cp.async helpers
// ---------------------------------------------------------------------------
__device__ __forceinline__ u64 pk2(float x) {
    u64 r; asm("mov.b64 %0, {%1, %1};" : "=l"(r) : "r"(__float_as_uint(x))); return r;
}
__device__ __forceinline__ void fma2(u64& d, u64 a, u64 b) {
    asm("fma.rn.f32x2 %0, %1, %2, %0;" : "+l"(d) : "l"(a), "l"(b));
}
__device__ __forceinline__ float2 up2(u64 u) {
    unsigned lo, hi; asm("mov.b64 {%0, %1}, %2;" : "=r"(lo), "=r"(hi) : "l"(u));
    return make_float2(__uint_as_float(lo), __uint_as_float(hi));
}
__device__ __forceinline__ void cpa16(float* smem, const float* g) {
    unsigned s = (unsigned)__cvta_generic_to_shared(smem);
    asm volatile("cp.async.cg.shared.global [%0], [%1], 16;" :: "r"(s), "l"(g));
}
__device__ __forceinline__ float sigmoidf_(float x) { return 1.f / (1.f + expf(-x)); }

// ---------------------------------------------------------------------------
// SGEMM + bias (unchanged — verified DRAM fix).
// MODE 0: A = x [B][S][I], M ordered m = t*64+b -> out gi[t][n][b].
// MODE 3: A = h1sq [t][k][b] (rows m = t*64+b)  -> out[b][t][n].
// ---------------------------------------------------------------------------
template <int MODE>
__global__ void __launch_bounds__(256)
sgemm_bias(const float* __restrict__ A, const float* __restrict__ Bw,
           const float* __restrict__ bias, float* __restrict__ out,
           int M, int N, int K)
{
    __shared__ float As[16][132];
    __shared__ float Bs[16][68];

    const int tid = threadIdx.x;
    const int m0  = blockIdx.y * 128;
    const int n0  = blockIdx.x * 64;
    const int tx  = tid & 15;
    const int ty  = tid >> 4;

    const float* Bb = Bw + (size_t)n0 * K;

    u64 acc[4][4];
#pragma unroll
    for (int i = 0; i < 4; i++)
#pragma unroll
        for (int j = 0; j < 4; j++) acc[i][j] = 0ull;

    const int lr = tid >> 2;
    const int lk = (tid & 3) * 4;
    const int t0 = m0 >> 6;
    const int kk = tid >> 4, qq = tid & 15;

    for (int kt = 0; kt < K; kt += 16) {
        if (MODE == 0) {
#pragma unroll
            for (int p = 0; p < 2; p++) {
                const int r = lr + p * 64;
                float4 v = *(const float4*)&A[((size_t)(r & 63) * S_ + t0 + (r >> 6)) * I_ + kt + lk];
                As[lk + 0][r] = v.x;
                As[lk + 1][r] = v.y;
                As[lk + 2][r] = v.z;
                As[lk + 3][r] = v.w;
            }
        } else {
            float4 v0 = *(const float4*)&A[(((size_t)t0       * 512) + kt + kk) * 64 + qq * 4];
            float4 v1 = *(const float4*)&A[(((size_t)(t0 + 1) * 512) + kt + kk) * 64 + qq * 4];
            *(float4*)&As[kk][qq * 4]      = v0;
            *(float4*)&As[kk][64 + qq * 4] = v1;
        }
        {
            float4 v = *(const float4*)&Bb[(size_t)lr * K + kt + lk];
            Bs[lk + 0][lr] = v.x;
            Bs[lk + 1][lr] = v.y;
            Bs[lk + 2][lr] = v.z;
            Bs[lk + 3][lr] = v.w;
        }
        __syncthreads();

#pragma unroll
        for (int k = 0; k < 16; k++) {
            float4 bv = *(const float4*)&Bs[k][tx * 4];
            u64 bp0 = pk2(bv.x), bp1 = pk2(bv.y), bp2 = pk2(bv.z), bp3 = pk2(bv.w);
            ulonglong2 a01 = *(const ulonglong2*)&As[k][ty * 8];
            ulonglong2 a23 = *(const ulonglong2*)&As[k][ty * 8 + 4];
            u64 ap[4] = {a01.x, a01.y, a23.x, a23.y};
#pragma unroll
            for (int i = 0; i < 4; i++) {
                fma2(acc[i][0], ap[i], bp0);
                fma2(acc[i][1], ap[i], bp1);
                fma2(acc[i][2], ap[i], bp2);
                fma2(acc[i][3], ap[i], bp3);
            }
        }
        __syncthreads();
    }

    float bv[4];
    *(float4*)bv = *(const float4*)&bias[n0 + tx * 4];

    if (MODE == 0) {
        const int t  = t0 + (ty >> 3);
        const int b0 = (ty & 7) * 8;
#pragma unroll
        for (int j = 0; j < 4; j++) {
            const int n = n0 + tx * 4 + j;
            float2 p0 = up2(acc[0][j]), p1 = up2(acc[1][j]);
            float2 p2 = up2(acc[2][j]), p3 = up2(acc[3][j]);
            float4 w0, w1;
            w0.x = p0.x + bv[j]; w0.y = p0.y + bv[j];
            w0.z = p1.x + bv[j]; w0.w = p1.y + bv[j];
            w1.x = p2.x + bv[j]; w1.y = p2.y + bv[j];
            w1.z = p3.x + bv[j]; w1.w = p3.y + bv[j];
            float* q = out + ((size_t)t * G3H + n) * B_ + b0;
            *(float4*)&q[0] = w0;
            *(float4*)&q[4] = w1;
        }
    } else {
        float accf[8][4];
#pragma unroll
        for (int i = 0; i < 4; i++)
#pragma unroll
            for (int j = 0; j < 4; j++) {
                float2 v = up2(acc[i][j]);
                accf[2 * i + 0][j] = v.x;
                accf[2 * i + 1][j] = v.y;
            }
#pragma unroll
        for (int i = 0; i < 8; i++) {
            int m = m0 + ty * 8 + i;
            int t = m >> 6, b = m & 63;
            float4 c;
            c.x = accf[i][0] + bv[0];
            c.y = accf[i][1] + bv[1];
            c.z = accf[i][2] + bv[2];
            c.w = accf[i][3] + bv[3];
            *(float4*)&out[((size_t)b * S_ + t) * O_ + n0 + tx * 4] = c;
        }
    }
}

// ---------------------------------------------------------------------------
// Fused two-layer GRU wavefront. 96 CTAs = 3 groups x 32 (16 j each), RT=256.
//  G0: h0[s] = cell(h0[s-1], gi0[s]);  G1: gi1[s-1] = h0[s-1]@W_ih1^T + b;
//  G2: h1[s-2] = cell(h1[s-3], gi1[s-2]).
// J-PAIRED f32x2: accumulator lanes = (j0, j1); weights load as natural pairs
// from smem (NO MOVs); h duplicated once per (k, 4b) and reused by 6 pairs.
// Thread = (ks, jq, bs): k-split 4 (k = 4m+ks interleave) x 4 jq x 16 bs,
// tile = 2 j-pairs x 3 gates x 4 b = 24 u64 accums.
// Full 128 KB h staged via 8 upfront cp.async groups, two wait points (R11).
// K-split reduced via padded smem scratch (stride 26 u64) in the dead h area.
// smem: hs 131072 B @0 | Wp (u64, j-paired) 98304 B @131072   = 229376 B
// ---------------------------------------------------------------------------
#define FUS_SMEM_BYTES 229376

__device__ __forceinline__ void compute_phase(const float* __restrict__ hp,
                                              const u64* __restrict__ wp,
                                              u64* __restrict__ acc)
{
#pragma unroll 8
    for (int m = 0; m < 64; m++) {
        float4 hv = *(const float4*)(hp + m * 256);    // k advances by 4 -> 256 floats
        u64 hd0 = pk2(hv.x), hd1 = pk2(hv.y), hd2 = pk2(hv.z), hd3 = pk2(hv.w);
        const u64* wb = wp + m * 96;                   // (k*4+jq)*6 advances 96
        ulonglong2 wA = *(const ulonglong2*)(wb);
        ulonglong2 wB = *(const ulonglong2*)(wb + 2);
        ulonglong2 wC = *(const ulonglong2*)(wb + 4);
        fma2(acc[ 0], hd0, wA.x); fma2(acc[ 1], hd1, wA.x);
        fma2(acc[ 2], hd2, wA.x); fma2(acc[ 3], hd3, wA.x);
        fma2(acc[ 4], hd0, wA.y); fma2(acc[ 5], hd1, wA.y);
        fma2(acc[ 6], hd2, wA.y); fma2(acc[ 7], hd3, wA.y);
        fma2(acc[ 8], hd0, wB.x); fma2(acc[ 9], hd1, wB.x);
        fma2(acc[10], hd2, wB.x); fma2(acc[11], hd3, wB.x);
        fma2(acc[12], hd0, wB.y); fma2(acc[13], hd1, wB.y);
        fma2(acc[14], hd2, wB.y); fma2(acc[15], hd3, wB.y);
        fma2(acc[16], hd0, wC.x); fma2(acc[17], hd1, wC.x);
        fma2(acc[18], hd2, wC.x); fma2(acc[19], hd3, wC.x);
        fma2(acc[20], hd0, wC.y); fma2(acc[21], hd1, wC.y);
        fma2(acc[22], hd2, wC.y); fma2(acc[23], hd3, wC.y);
    }
}

__global__ void __launch_bounds__(RT, 1)
gru_fused(const float* __restrict__ gi0,
          const float* __restrict__ Whh0, const float* __restrict__ bhh0,
          const float* __restrict__ Wih1, const float* __restrict__ bih1,
          const float* __restrict__ Whh1, const float* __restrict__ bhh1,
          float* __restrict__ hid)    // [2][B][H] tail of d_out
{
    extern __shared__ float sm[];
    float* hs = sm;                                  // 131072 B (full h state)
    u64*   Wp = (u64*)((char*)sm + 131072);          // 98304 B, [k][jq][p*3+g]

    const int tid   = threadIdx.x;
    const int cta   = blockIdx.x;
    const int grp   = cta >> 5;
    const int lc    = cta & 31;
    const int jbase = lc * 16;

    const float* Wsrc = (grp == 0) ? Whh0 : (grp == 1) ? Wih1 : Whh1;

    // J-paired weight preload: Wp[(k*4+jq)*6 + (p*3+g)] = (w[j0], w[j1]),
    // j0 = jbase + jq*4 + p*2, j1 = j0+1.
    for (int i = tid; i < 12288; i += RT) {
        int w6   = i % 6;
        int rest = i / 6;
        int jq   = rest & 3;
        int k    = rest >> 2;
        int p = w6 / 3, g = w6 % 3;
        int j0 = jbase + jq * 4 + p * 2;
        float w0 = Wsrc[(size_t)(g * 512 + j0)     * 512 + k];
        float w1 = Wsrc[(size_t)(g * 512 + j0 + 1) * 512 + k];
        Wp[i] = (u64)__float_as_uint(w0) | ((u64)__float_as_uint(w1) << 32);
    }

    // Compute mapping
    const int ks = tid >> 6;          // 0..3 k-split
    const int jq = (tid >> 4) & 3;    // 0..3
    const int bs = tid & 15;          // 0..15
    const int bA = bs * 4;

    // Finalize mapping (same shape as R11 epilogue)
    const int fjl = tid >> 4;         // 0..15
    const int fbs = tid & 15;
    const int fbA = fbs * 4;
    const int fj  = jbase + fjl;
    const int fq  = fjl >> 2;
    const int fp  = (fjl >> 1) & 1;
    const int fe  = fjl & 1;

    float br = 0.f, bz = 0.f, bn = 0.f;
    if (grp == 0) { br = bhh0[fj]; bz = bhh0[512 + fj]; bn = bhh0[1024 + fj]; }
    if (grp == 1) { br = bih1[fj]; bz = bih1[512 + fj]; bn = bih1[1024 + fj]; }
    if (grp == 2) { br = bhh1[fj]; bz = bhh1[512 + fj]; bn = bhh1[1024 + fj]; }

    __syncthreads();

    for (int s = 0; s < STEPS; s++) {
        const bool active = (grp == 0) ? (s < 1024)
                          : (grp == 1) ? (s >= 1 && s < 1025)
                                       : (s >= 2);
        if (active) {
            const float* hsrc = ((grp == 2) ? g_h1T : g_h0T)
                              + (((grp == 2 ? s - 2 : s) + 1) & 1) * (H_ * B_);

            // Issue ALL 8 chunk groups (16 KB each) covering the full h state.
#pragma unroll
            for (int c = 0; c < 8; c++) {
                const float* s4 = hsrc + c * 4096;
                float*       d4 = hs   + c * 4096;
#pragma unroll
                for (int u = 0; u < 4; u++)
                    cpa16(d4 + (tid + u * RT) * 4, s4 + (tid + u * RT) * 4);
                asm volatile("cp.async.commit_group;");
            }

            // Prefetch gi + h_old via LDG with FINALIZE indices (lands under compute)
            float GIR[4], GIZ[4], GIN[4], hold[4];
            if (grp != 1) {
                const float* p = (grp == 0)
                    ? gi0   + (size_t)s * (G3H * 64)
                    : g_gi1 + (size_t)(s & 1) * (G3H * 64);
                *(float4*)&GIR[0]  = *(const float4*)&p[(size_t)fj          * 64 + fbA];
                *(float4*)&GIZ[0]  = *(const float4*)&p[(size_t)(512 + fj)  * 64 + fbA];
                *(float4*)&GIN[0]  = *(const float4*)&p[(size_t)(1024 + fj) * 64 + fbA];
                *(float4*)&hold[0] = *(const float4*)&hsrc[fj * 64 + fbA];
            }

            u64 acc[24];
#pragma unroll
            for (int i = 0; i < 24; i++) acc[i] = 0ull;

            // Phase 0: k = 4m + ks, m<64  (all < 256; chunks 0-3)
            asm volatile("cp.async.wait_group 4;");
            __syncthreads();
            compute_phase(hs + (size_t)ks * 64 + bA,
                          Wp + ((size_t)ks * 4 + jq) * 6, acc);

            // Phase 1: k = 256 + 4m + ks  (chunks 4-7)
            asm volatile("cp.async.wait_group 0;");
            __syncthreads();
            compute_phase(hs + (size_t)(256 + ks) * 64 + bA,
                          Wp + ((size_t)(256 + ks) * 4 + jq) * 6, acc);

            // K-split reduce via padded smem scratch in dead h region.
            // P stride 26 u64 (208 B), 256*26*8 = 53248 B < 64 KB (chunks 0-3
            // region, no longer read).
            u64* P = (u64*)hs;
            {
                u64* pp = P + (size_t)tid * 26;
#pragma unroll
                for (int q2 = 0; q2 < 12; q2++)
                    *(ulonglong2*)(pp + q2 * 2) =
                        make_ulonglong2(acc[q2 * 2], acc[q2 * 2 + 1]);
            }
            __syncthreads();

            // Finalize: thread (fj, fbA..fbA+3); gather 4 k-split partials.
            float Rg[4], Zg[4], Ng[4];
#pragma unroll
            for (int g = 0; g < 3; g++) {
                float Sv[4] = {0.f, 0.f, 0.f, 0.f};
#pragma unroll
                for (int kss = 0; kss < 4; kss++) {
                    const u64* qb = P + (size_t)(kss * 64 + fq * 16 + fbs) * 26
                                      + (fp * 3 + g) * 4;
                    ulonglong2 u01 = *(const ulonglong2*)qb;
                    ulonglong2 u23 = *(const ulonglong2*)(qb + 2);
                    float2 f0 = up2(u01.x), f1 = up2(u01.y);
                    float2 f2 = up2(u23.x), f3 = up2(u23.y);
                    Sv[0] += fe ? f0.y : f0.x;
                    Sv[1] += fe ? f1.y : f1.x;
                    Sv[2] += fe ? f2.y : f2.x;
                    Sv[3] += fe ? f3.y : f3.x;
                }
                if (g == 0) { Rg[0]=Sv[0]; Rg[1]=Sv[1]; Rg[2]=Sv[2]; Rg[3]=Sv[3]; }
                else if (g == 1) { Zg[0]=Sv[0]; Zg[1]=Sv[1]; Zg[2]=Sv[2]; Zg[3]=Sv[3]; }
                else { Ng[0]=Sv[0]; Ng[1]=Sv[1]; Ng[2]=Sv[2]; Ng[3]=Sv[3]; }
            }

            if (grp == 1) {
                float* q = g_gi1 + (size_t)((s - 1) & 1) * (G3H * 64);
                float o[4];
#pragma unroll
                for (int i = 0; i < 4; i++) o[i] = Rg[i] + br;
                *(float4*)&q[(size_t)fj * 64 + fbA] = *(float4*)&o[0];
#pragma unroll
                for (int i = 0; i < 4; i++) o[i] = Zg[i] + bz;
                *(float4*)&q[(size_t)(512 + fj) * 64 + fbA] = *(float4*)&o[0];
#pragma unroll
                for (int i = 0; i < 4; i++) o[i] = Ng[i] + bn;
                *(float4*)&q[(size_t)(1024 + fj) * 64 + fbA] = *(float4*)&o[0];
            } else {
                float hn[4];
#pragma unroll
                for (int i = 0; i < 4; i++) {
                    float r_ = sigmoidf_(GIR[i] + Rg[i] + br);
                    float z_ = sigmoidf_(GIZ[i] + Zg[i] + bz);
                    float n_ = tanhf(GIN[i] + r_ * (Ng[i] + bn));
                    hn[i] = (1.f - z_) * n_ + z_ * hold[i];
                }

                const int tau = (grp == 2) ? s - 2 : s;
                float* hdT = ((grp == 2) ? g_h1T : g_h0T) + (tau & 1) * (H_ * B_);
                *(float4*)&hdT[fj * 64 + fbA] = *(float4*)&hn[0];

                if (grp == 2) {
                    float* hq = g_h1sq + (size_t)tau * (H_ * B_);
                    *(float4*)&hq[fj * 64 + fbA] = *(float4*)&hn[0];
                }
                if (tau == S_ - 1) {
                    float* hd = hid + (grp == 2 ? B_ * H_ : 0);
#pragma unroll
                    for (int i = 0; i < 4; i++)
                        hd[(size_t)(fbA + i) * H_ + fj] = hn[i];
                }
            }
        }

        // ---- two-level grid barrier (known-good) ----
        __syncthreads();
        if (tid == 0) {
            __threadfence();
            unsigned go = atomicAdd(&g_sync[(cta >> 3) * 32], 1u);
            if (go == (unsigned)(s + 1) * 8 - 1) {
                unsigned ro = atomicAdd(&g_sync[400], 1u);
                if (ro == (unsigned)(s + 1) * 12 - 1) {
                    __threadfence();
                    *((volatile unsigned*)&g_sync[416]) = (unsigned)(s + 1);
                }
            }
            while (*((volatile unsigned*)&g_sync[416]) < (unsigned)(s + 1)) { }
            __threadfence();
        }
        __syncthreads();
    }
}

// ---------------------------------------------------------------------------
// Launch
// ---------------------------------------------------------------------------
extern "C" void kernel_launch(void* const* d_in, const int* in_sizes, int n_in,
                              void* d_out, int out_size)
{
    const float* x    = (const float*)d_in[0];
    const float* Wih0 = (const float*)d_in[1];
    const float* Whh0 = (const float*)d_in[2];
    const float* bih0 = (const float*)d_in[3];
    const float* bhh0 = (const float*)d_in[4];
    const float* Wih1 = (const float*)d_in[5];
    const float* Whh1 = (const float*)d_in[6];
    const float* bih1 = (const float*)d_in[7];
    const float* bhh1 = (const float*)d_in[8];
    const float* Wfc  = (const float*)d_in[9];
    const float* bfc  = (const float*)d_in[10];

    float* out = (float*)d_out;                    // logits [B][S][O]
    float* hid = out + (size_t)B_ * S_ * O_;       // hidden [2][B][H]

    float *gi0, *h1sq, *h0T, *h1T;
    unsigned* sy;
    cudaGetSymbolAddress((void**)&gi0,  g_gi0);
    cudaGetSymbolAddress((void**)&h1sq, g_h1sq);
    cudaGetSymbolAddress((void**)&h0T,  g_h0T);
    cudaGetSymbolAddress((void**)&h1T,  g_h1T);
    cudaGetSymbolAddress((void**)&sy,   g_sync);

    cudaFuncSetAttribute(gru_fused, cudaFuncAttributeMaxDynamicSharedMemorySize,
                         FUS_SMEM_BYTES);

    const int M = B_ * S_;
    dim3 blk(256);
    dim3 gGI(G3H / 64, M / 128);   // 24 x 512
    dim3 gFC(O_ / 64, M / 128);    //  8 x 512

    // gi0 = x @ W_ih0^T + b_ih0   -> [t][row][b]  (coalesced b-axis stores)
    sgemm_bias<0><<<gGI, blk>>>(x, Wih0, bih0, gi0, M, G3H, I_);

    cudaMemsetAsync(h0T, 0, (size_t)2 * H_ * B_ * sizeof(float));
    cudaMemsetAsync(h1T, 0, (size_t)2 * H_ * B_ * sizeof(float));
    cudaMemsetAsync(sy, 0, 512 * sizeof(unsigned));

    gru_fused<<<GR, RT, FUS_SMEM_BYTES>>>(gi0, Whh0, bhh0, Wih1, bih1,
                                          Whh1, bhh1, hid);

    // logits = hseq1 @ W_fc^T + b_fc   (A read from transposed [t][j][b])
    sgemm_bias<3><<<gFC, blk>>>(h1sq, Wfc, bfc, out, M, O_, H_);
}

// round 16
// speedup vs baseline: 1.4999x; 1.0393x over previous
#include <cuda_runtime.h>
#include <cstdint>
#include <math.h>

#define B_   64
#define S_   1024
#define I_   256
#define H_   512
#define O_   512
#define G3H  1536

#define GR    148    // 3 gru groups x 32 + 52 FC rider CTAs; all wave-1 resident
#define RT    256    // 8 warps -> 2 per SMSP
#define STEPS 1059   // 1026 wavefront + FC-rider tail (last tile 1023 done at 1058)

typedef unsigned long long u64;

// ---------------------------------------------------------------------------
// Device-global scratch
// ---------------------------------------------------------------------------
__device__ float    g_gi0  [(size_t)S_ * G3H * B_];   // gi0 [t][row][b]
__device__ float    g_gi1  [2 * G3H * B_];            // gi1 ring [slot][row][b]
__device__ float    g_h1sq [(size_t)S_ * H_ * B_];    // hseq1 transposed [t][j][b]
__device__ float    g_h0T  [2 * H_ * B_];             // h0 double buffer [slot][j][b]
__device__ float    g_h1T  [2 * H_ * B_];             // h1 double buffer [slot][j][b]
__device__ unsigned g_sync [1024];                    // leaves @ g*32 (g 0..18), root @800, release @832

// ---------------------------------------------------------------------------
// f32x2 + cp.async helpers
// ---------------------------------------------------------------------------
__device__ __forceinline__ u64 pk2(float x) {
    u64 r; asm("mov.b64 %0, {%1, %1};" : "=l"(r) : "r"(__float_as_uint(x))); return r;
}
__device__ __forceinline__ void fma2(u64& d, u64 a, u64 b) {
    asm("fma.rn.f32x2 %0, %1, %2, %0;" : "+l"(d) : "l"(a), "l"(b));
}
__device__ __forceinline__ float2 up2(u64 u) {
    unsigned lo, hi; asm("mov.b64 {%0, %1}, %2;" : "=r"(lo), "=r"(hi) : "l"(u));
    return make_float2(__uint_as_float(lo), __uint_as_float(hi));
}
__device__ __forceinline__ void cpa16(float* smem, const float* g) {
    unsigned s = (unsigned)__cvta_generic_to_shared(smem);
    asm volatile("cp.async.cg.shared.global [%0], [%1], 16;" :: "r"(s), "l"(g));
}
// Fast gates: ex2.approx + rcp.approx (no libm calls). Err ~1e-7 rel.
__device__ __forceinline__ float sigf(float x) {
    return __fdividef(1.f, 1.f + __expf(-x));
}
__device__ __forceinline__ float tanhf_(float x) {
    return __fdividef(2.f, 1.f + __expf(-2.f * x)) - 1.f;
}

// ---------------------------------------------------------------------------
// SGEMM + bias (MODE 0 only — verified DRAM-coalesced epilogue).
// A = x [B][S][I], M ordered m = t*64+b -> out gi[t][n][b].
// ---------------------------------------------------------------------------
template <int MODE>
__global__ void __launch_bounds__(256)
sgemm_bias(const float* __restrict__ A, const float* __restrict__ Bw,
           const float* __restrict__ bias, float* __restrict__ out,
           int M, int N, int K)
{
    __shared__ float As[16][132];
    __shared__ float Bs[16][68];

    const int tid = threadIdx.x;
    const int m0  = blockIdx.y * 128;
    const int n0  = blockIdx.x * 64;
    const int tx  = tid & 15;
    const int ty  = tid >> 4;

    const float* Bb = Bw + (size_t)n0 * K;

    u64 acc[4][4];
#pragma unroll
    for (int i = 0; i < 4; i++)
#pragma unroll
        for (int j = 0; j < 4; j++) acc[i][j] = 0ull;

    const int lr = tid >> 2;
    const int lk = (tid & 3) * 4;
    const int t0 = m0 >> 6;

    for (int kt = 0; kt < K; kt += 16) {
#pragma unroll
        for (int p = 0; p < 2; p++) {
            const int r = lr + p * 64;
            float4 v = *(const float4*)&A[((size_t)(r & 63) * S_ + t0 + (r >> 6)) * I_ + kt + lk];
            As[lk + 0][r] = v.x;
            As[lk + 1][r] = v.y;
            As[lk + 2][r] = v.z;
            As[lk + 3][r] = v.w;
        }
        {
            float4 v = *(const float4*)&Bb[(size_t)lr * K + kt + lk];
            Bs[lk + 0][lr] = v.x;
            Bs[lk + 1][lr] = v.y;
            Bs[lk + 2][lr] = v.z;
            Bs[lk + 3][lr] = v.w;
        }
        __syncthreads();

#pragma unroll
        for (int k = 0; k < 16; k++) {
            float4 bv = *(const float4*)&Bs[k][tx * 4];
            u64 bp0 = pk2(bv.x), bp1 = pk2(bv.y), bp2 = pk2(bv.z), bp3 = pk2(bv.w);
            ulonglong2 a01 = *(const ulonglong2*)&As[k][ty * 8];
            ulonglong2 a23 = *(const ulonglong2*)&As[k][ty * 8 + 4];
            u64 ap[4] = {a01.x, a01.y, a23.x, a23.y};
#pragma unroll
            for (int i = 0; i < 4; i++) {
                fma2(acc[i][0], ap[i], bp0);
                fma2(acc[i][1], ap[i], bp1);
                fma2(acc[i][2], ap[i], bp2);
                fma2(acc[i][3], ap[i], bp3);
            }
        }
        __syncthreads();
    }

    float bv[4];
    *(float4*)bv = *(const float4*)&bias[n0 + tx * 4];

    const int t  = t0 + (ty >> 3);
    const int b0 = (ty & 7) * 8;
#pragma unroll
    for (int j = 0; j < 4; j++) {
        const int n = n0 + tx * 4 + j;
        float2 p0 = up2(acc[0][j]), p1 = up2(acc[1][j]);
        float2 p2 = up2(acc[2][j]), p3 = up2(acc[3][j]);
        float4 w0, w1;
        w0.x = p0.x + bv[j]; w0.y = p0.y + bv[j];
        w0.z = p1.x + bv[j]; w0.w = p1.y + bv[j];
        w1.x = p2.x + bv[j]; w1.y = p2.y + bv[j];
        w1.z = p3.x + bv[j]; w1.w = p3.y + bv[j];
        float* q = out + ((size_t)t * G3H + n) * B_ + b0;
        *(float4*)&q[0] = w0;
        *(float4*)&q[4] = w1;
    }
}

// ---------------------------------------------------------------------------
// Fused two-layer GRU wavefront + FC rider. 148 CTAs:
//  G0 (cta  0..31): h0[s]    = cell(h0[s-1], gi0[s])       s in [0,1024)
//  G1 (cta 32..63): gi1[s-1] = h0[s-1]@W_ih1^T + b          s in [1,1025)
//  G2 (cta 64..95): h1[s-2]  = cell(h1[s-3], gi1[s-2])      s in [2,1026)
//  G3 (cta 96..147): FC rider — CTA c3 owns tiles t=c3+52m; per tile,
//     stage h1sq[t] (128 KB) at step t+3, then 32 steps x 16 FC columns
//     (Wfc chunks double-buffered 1 step ahead); logits via smem transpose.
// GRU mainloop: j-paired f32x2 (R15 verified), k-split 4, smem reduce.
// gru smem: hs 131072 @0 | Wp 98304 @131072
// G3  smem: htile 131072 @0 | wbuf 2x32768 @131072 | scratch 4096 @196608
// ---------------------------------------------------------------------------
#define FUS_SMEM_BYTES 229376

__device__ __forceinline__ void compute_phase(const float* __restrict__ hp,
                                              const u64* __restrict__ wp,
                                              u64* __restrict__ acc)
{
#pragma unroll 8
    for (int m = 0; m < 64; m++) {
        float4 hv = *(const float4*)(hp + m * 256);    // k advances by 4
        u64 hd0 = pk2(hv.x), hd1 = pk2(hv.y), hd2 = pk2(hv.z), hd3 = pk2(hv.w);
        const u64* wb = wp + m * 96;
        ulonglong2 wA = *(const ulonglong2*)(wb);
        ulonglong2 wB = *(const ulonglong2*)(wb + 2);
        ulonglong2 wC = *(const ulonglong2*)(wb + 4);
        fma2(acc[ 0], hd0, wA.x); fma2(acc[ 1], hd1, wA.x);
        fma2(acc[ 2], hd2, wA.x); fma2(acc[ 3], hd3, wA.x);
        fma2(acc[ 4], hd0, wA.y); fma2(acc[ 5], hd1, wA.y);
        fma2(acc[ 6], hd2, wA.y); fma2(acc[ 7], hd3, wA.y);
        fma2(acc[ 8], hd0, wB.x); fma2(acc[ 9], hd1, wB.x);
        fma2(acc[10], hd2, wB.x); fma2(acc[11], hd3, wB.x);
        fma2(acc[12], hd0, wB.y); fma2(acc[13], hd1, wB.y);
        fma2(acc[14], hd2, wB.y); fma2(acc[15], hd3, wB.y);
        fma2(acc[16], hd0, wC.x); fma2(acc[17], hd1, wC.x);
        fma2(acc[18], hd2, wC.x); fma2(acc[19], hd3, wC.x);
        fma2(acc[20], hd0, wC.y); fma2(acc[21], hd1, wC.y);
        fma2(acc[22], hd2, wC.y); fma2(acc[23], hd3, wC.y);
    }
}

__global__ void __launch_bounds__(RT, 1)
gru_fused(const float* __restrict__ gi0,
          const float* __restrict__ Whh0, const float* __restrict__ bhh0,
          const float* __restrict__ Wih1, const float* __restrict__ bih1,
          const float* __restrict__ Whh1, const float* __restrict__ bhh1,
          const float* __restrict__ Wfc,  const float* __restrict__ bfc,
          float* __restrict__ logits,     // [B][S][O]
          float* __restrict__ hid)        // [2][B][H]
{
    extern __shared__ float sm[];
    float* hs = sm;                                  // gru: 131072 B h | G3: htile
    u64*   Wp = (u64*)((char*)sm + 131072);          // gru: 98304 B weights
    float* wbuf    = sm + 32768;                     // G3: 2 x 32768 B @131072
    float* scratch = sm + 49152;                     // G3: 4096 B @196608

    const int tid   = threadIdx.x;
    const int cta   = blockIdx.x;
    const int grp   = (cta < 96) ? (cta >> 5) : 3;
    const int lc    = cta & 31;
    const int jbase = lc * 16;

    // ---- GRU weight preload (grp 0-2 only) ----
    if (grp < 3) {
        const float* Wsrc = (grp == 0) ? Whh0 : (grp == 1) ? Wih1 : Whh1;
        for (int i = tid; i < 12288; i += RT) {
            int w6   = i % 6;
            int rest = i / 6;
            int jq   = rest & 3;
            int k    = rest >> 2;
            int p = w6 / 3, g = w6 % 3;
            int j0 = jbase + jq * 4 + p * 2;
            float w0 = Wsrc[(size_t)(g * 512 + j0)     * 512 + k];
            float w1 = Wsrc[(size_t)(g * 512 + j0 + 1) * 512 + k];
            Wp[i] = (u64)__float_as_uint(w0) | ((u64)__float_as_uint(w1) << 32);
        }
    }

    // GRU compute mapping
    const int ks = tid >> 6;
    const int jq = (tid >> 4) & 3;
    const int bs = tid & 15;
    const int bA = bs * 4;

    // GRU finalize mapping
    const int fjl = tid >> 4;
    const int fbs = tid & 15;
    const int fbA = fbs * 4;
    const int fj  = jbase + fjl;
    const int fq  = fjl >> 2;
    const int fp  = (fjl >> 1) & 1;
    const int fe  = fjl & 1;

    float br = 0.f, bz = 0.f, bn = 0.f;
    if (grp == 0) { br = bhh0[fj]; bz = bhh0[512 + fj]; bn = bhh0[1024 + fj]; }
    if (grp == 1) { br = bih1[fj]; bz = bih1[512 + fj]; bn = bih1[1024 + fj]; }
    if (grp == 2) { br = bhh1[fj]; bz = bhh1[512 + fj]; bn = bhh1[1024 + fj]; }

    // G3 mapping
    const int nsub = tid >> 5;         // 0..7 (warp id)
    const int bp   = tid & 31;         // b-pair
    int cur_t = cta - 96;              // G3 tile cursor

    __syncthreads();

    for (int s = 0; s < STEPS; s++) {
        if (grp < 3) {
            const bool active = (grp == 0) ? (s < 1024)
                              : (grp == 1) ? (s >= 1 && s < 1025)
                                           : (s >= 2 && s < 1026);
            if (active) {
                const float* hsrc = ((grp == 2) ? g_h1T : g_h0T)
                                  + (((grp == 2 ? s - 2 : s) + 1) & 1) * (H_ * B_);

                // Issue all 8 chunk groups (16 KB each) of the full h state.
#pragma unroll
                for (int c = 0; c < 8; c++) {
                    const float* s4 = hsrc + c * 4096;
                    float*       d4 = hs   + c * 4096;
#pragma unroll
                    for (int u = 0; u < 4; u++)
                        cpa16(d4 + (tid + u * RT) * 4, s4 + (tid + u * RT) * 4);
                    asm volatile("cp.async.commit_group;");
                }

                float GIR[4], GIZ[4], GIN[4], hold[4];
                if (grp != 1) {
                    const float* p = (grp == 0)
                        ? gi0   + (size_t)s * (G3H * 64)
                        : g_gi1 + (size_t)(s & 1) * (G3H * 64);
                    *(float4*)&GIR[0]  = *(const float4*)&p[(size_t)fj          * 64 + fbA];
                    *(float4*)&GIZ[0]  = *(const float4*)&p[(size_t)(512 + fj)  * 64 + fbA];
                    *(float4*)&GIN[0]  = *(const float4*)&p[(size_t)(1024 + fj) * 64 + fbA];
                    *(float4*)&hold[0] = *(const float4*)&hsrc[fj * 64 + fbA];
                }

                u64 acc[24];
#pragma unroll
                for (int i = 0; i < 24; i++) acc[i] = 0ull;

                asm volatile("cp.async.wait_group 4;");
                __syncthreads();
                compute_phase(hs + (size_t)ks * 64 + bA,
                              Wp + ((size_t)ks * 4 + jq) * 6, acc);

                asm volatile("cp.async.wait_group 0;");
                __syncthreads();
                compute_phase(hs + (size_t)(256 + ks) * 64 + bA,
                              Wp + ((size_t)(256 + ks) * 4 + jq) * 6, acc);

                // K-split reduce via padded smem scratch (dead h region)
                u64* P = (u64*)hs;
                {
                    u64* pp = P + (size_t)tid * 26;
#pragma unroll
                    for (int q2 = 0; q2 < 12; q2++)
                        *(ulonglong2*)(pp + q2 * 2) =
                            make_ulonglong2(acc[q2 * 2], acc[q2 * 2 + 1]);
                }
                __syncthreads();

                float Rg[4], Zg[4], Ng[4];
#pragma unroll
                for (int g = 0; g < 3; g++) {
                    float Sv[4] = {0.f, 0.f, 0.f, 0.f};
#pragma unroll
                    for (int kss = 0; kss < 4; kss++) {
                        const u64* qb = P + (size_t)(kss * 64 + fq * 16 + fbs) * 26
                                          + (fp * 3 + g) * 4;
                        ulonglong2 u01 = *(const ulonglong2*)qb;
                        ulonglong2 u23 = *(const ulonglong2*)(qb + 2);
                        float2 f0 = up2(u01.x), f1 = up2(u01.y);
                        float2 f2 = up2(u23.x), f3 = up2(u23.y);
                        Sv[0] += fe ? f0.y : f0.x;
                        Sv[1] += fe ? f1.y : f1.x;
                        Sv[2] += fe ? f2.y : f2.x;
                        Sv[3] += fe ? f3.y : f3.x;
                    }
                    if (g == 0)      { Rg[0]=Sv[0]; Rg[1]=Sv[1]; Rg[2]=Sv[2]; Rg[3]=Sv[3]; }
                    else if (g == 1) { Zg[0]=Sv[0]; Zg[1]=Sv[1]; Zg[2]=Sv[2]; Zg[3]=Sv[3]; }
                    else             { Ng[0]=Sv[0]; Ng[1]=Sv[1]; Ng[2]=Sv[2]; Ng[3]=Sv[3]; }
                }

                if (grp == 1) {
                    float* q = g_gi1 + (size_t)((s - 1) & 1) * (G3H * 64);
                    float o[4];
#pragma unroll
                    for (int i = 0; i < 4; i++) o[i] = Rg[i] + br;
                    *(float4*)&q[(size_t)fj * 64 + fbA] = *(float4*)&o[0];
#pragma unroll
                    for (int i = 0; i < 4; i++) o[i] = Zg[i] + bz;
                    *(float4*)&q[(size_t)(512 + fj) * 64 + fbA] = *(float4*)&o[0];
#pragma unroll
                    for (int i = 0; i < 4; i++) o[i] = Ng[i] + bn;
                    *(float4*)&q[(size_t)(1024 + fj) * 64 + fbA] = *(float4*)&o[0];
                } else {
                    float hn[4];
#pragma unroll
                    for (int i = 0; i < 4; i++) {
                        float r_ = sigf(GIR[i] + Rg[i] + br);
                        float z_ = sigf(GIZ[i] + Zg[i] + bz);
                        float n_ = tanhf_(GIN[i] + r_ * (Ng[i] + bn));
                        hn[i] = (1.f - z_) * n_ + z_ * hold[i];
                    }

                    const int tau = (grp == 2) ? s - 2 : s;
                    float* hdT = ((grp == 2) ? g_h1T : g_h0T) + (tau & 1) * (H_ * B_);
                    *(float4*)&hdT[fj * 64 + fbA] = *(float4*)&hn[0];

                    if (grp == 2) {
                        float* hq = g_h1sq + (size_t)tau * (H_ * B_);
                        *(float4*)&hq[fj * 64 + fbA] = *(float4*)&hn[0];
                    }
                    if (tau == S_ - 1) {
                        float* hd = hid + (grp == 2 ? B_ * H_ : 0);
#pragma unroll
                        for (int i = 0; i < 4; i++)
                            hd[(size_t)(fbA + i) * H_ + fj] = hn[i];
                    }
                }
            }
        } else {
            // ================= G3: FC rider =================
            if (cur_t <= 1023) {
                if (s == cur_t + 3) {
                    // Stage h tile (128 KB) + Wfc chunk 0 (32 KB), ONE group.
                    const float* hsrcT = g_h1sq + (size_t)cur_t * (H_ * B_);
#pragma unroll
                    for (int u = 0; u < 32; u++)
                        cpa16(hs + (tid + u * RT) * 4, hsrcT + (tid + u * RT) * 4);
                    const float* wsrc = Wfc;   // cols [0,16): rows 0..15
#pragma unroll
                    for (int u = 0; u < 8; u++)
                        cpa16(wbuf + (tid + u * RT) * 4, wsrc + (tid + u * RT) * 4);
                    asm volatile("cp.async.commit_group;");
                } else if (s >= cur_t + 4 && s < cur_t + 36) {
                    const int q = s - (cur_t + 4);     // chunk 0..31
                    const int nc0 = q * 16;
                    // Prefetch next chunk's Wfc into the other buffer
                    if (q + 1 < 32) {
                        const float* wsrc = Wfc + (size_t)(nc0 + 16) * 512;
                        float* wd = wbuf + ((q + 1) & 1) * 8192;
#pragma unroll
                        for (int u = 0; u < 8; u++)
                            cpa16(wd + (tid + u * RT) * 4, wsrc + (tid + u * RT) * 4);
                        asm volatile("cp.async.commit_group;");
                        asm volatile("cp.async.wait_group 1;");
                    } else {
                        asm volatile("cp.async.wait_group 0;");
                    }
                    __syncthreads();

                    // Compute 16 cols x 64 b: thread = (nsub warp, bp lane),
                    // 2 n per thread, b-paired f32x2 accumulation over k.
                    const float* w0p = wbuf + (q & 1) * 8192 + (nsub * 2) * 512;
                    const float* w1p = w0p + 512;
                    u64 a0 = 0ull, a1 = 0ull;
#pragma unroll 4
                    for (int k = 0; k < 512; k += 4) {
                        float4 w0 = *(const float4*)&w0p[k];
                        float4 w1 = *(const float4*)&w1p[k];
                        u64 h0 = *(const u64*)&hs[(k + 0) * 64 + bp * 2];
                        u64 h1 = *(const u64*)&hs[(k + 1) * 64 + bp * 2];
                        u64 h2 = *(const u64*)&hs[(k + 2) * 64 + bp * 2];
                        u64 h3 = *(const u64*)&hs[(k + 3) * 64 + bp * 2];
                        fma2(a0, h0, pk2(w0.x)); fma2(a1, h0, pk2(w1.x));
                        fma2(a0, h1, pk2(w0.y)); fma2(a1, h1, pk2(w1.y));
                        fma2(a0, h2, pk2(w0.z)); fma2(a1, h2, pk2(w1.z));
                        fma2(a0, h3, pk2(w0.w)); fma2(a1, h3, pk2(w1.w));
                    }
                    const int n0 = nc0 + nsub * 2;
                    float bb0 = bfc[n0], bb1 = bfc[n0 + 1];
                    float2 v0 = up2(a0), v1 = up2(a1);
                    scratch[(nsub * 2 + 0) * 64 + bp * 2]     = v0.x + bb0;
                    scratch[(nsub * 2 + 0) * 64 + bp * 2 + 1] = v0.y + bb0;
                    scratch[(nsub * 2 + 1) * 64 + bp * 2]     = v1.x + bb1;
                    scratch[(nsub * 2 + 1) * 64 + bp * 2 + 1] = v1.y + bb1;
                    __syncthreads();

                    // Transposed store: thread = (b, nq); STG.128 along n.
                    {
                        const int b  = tid >> 2;
                        const int nq = tid & 3;
                        float4 o;
                        o.x = scratch[(nq * 4 + 0) * 64 + b];
                        o.y = scratch[(nq * 4 + 1) * 64 + b];
                        o.z = scratch[(nq * 4 + 2) * 64 + b];
                        o.w = scratch[(nq * 4 + 3) * 64 + b];
                        *(float4*)&logits[((size_t)b * S_ + cur_t) * O_ + nc0 + nq * 4] = o;
                    }
                    __syncthreads();   // protect scratch before next step reuse

                    if (q == 31) cur_t += 52;
                }
            }
        }

        // ---- two-level grid barrier over 148 CTAs (19 leaves; last has 4) ----
        __syncthreads();
        if (tid == 0) {
            __threadfence();
            const int lg  = cta >> 3;
            const unsigned gsz = (lg == 18) ? 4u : 8u;
            unsigned go = atomicAdd(&g_sync[lg * 32], 1u);
            if (go == (unsigned)(s + 1) * gsz - 1) {
                unsigned ro = atomicAdd(&g_sync[800], 1u);
                if (ro == (unsigned)(s + 1) * 19 - 1) {
                    __threadfence();
                    *((volatile unsigned*)&g_sync[832]) = (unsigned)(s + 1);
                }
            }
            while (*((volatile unsigned*)&g_sync[832]) < (unsigned)(s + 1)) { }
            __threadfence();
        }
        __syncthreads();
    }
}

// ---------------------------------------------------------------------------
// Launch
// ---------------------------------------------------------------------------
extern "C" void kernel_launch(void* const* d_in, const int* in_sizes, int n_in,
                              void* d_out, int out_size)
{
    const float* x    = (const float*)d_in[0];
    const float* Wih0 = (const float*)d_in[1];
    const float* Whh0 = (const float*)d_in[2];
    const float* bih0 = (const float*)d_in[3];
    const float* bhh0 = (const float*)d_in[4];
    const float* Wih1 = (const float*)d_in[5];
    const float* Whh1 = (const float*)d_in[6];
    const float* bih1 = (const float*)d_in[7];
    const float* bhh1 = (const float*)d_in[8];
    const float* Wfc  = (const float*)d_in[9];
    const float* bfc  = (const float*)d_in[10];

    float* out = (float*)d_out;                    // logits [B][S][O]
    float* hid = out + (size_t)B_ * S_ * O_;       // hidden [2][B][H]

    float *gi0, *h0T, *h1T;
    unsigned* sy;
    cudaGetSymbolAddress((void**)&gi0,  g_gi0);
    cudaGetSymbolAddress((void**)&h0T,  g_h0T);
    cudaGetSymbolAddress((void**)&h1T,  g_h1T);
    cudaGetSymbolAddress((void**)&sy,   g_sync);

    cudaFuncSetAttribute(gru_fused, cudaFuncAttributeMaxDynamicSharedMemorySize,
                         FUS_SMEM_BYTES);

    const int M = B_ * S_;
    dim3 blk(256);
    dim3 gGI(G3H / 64, M / 128);   // 24 x 512

    // gi0 = x @ W_ih0^T + b_ih0   -> [t][row][b]
    sgemm_bias<0><<<gGI, blk>>>(x, Wih0, bih0, gi0, M, G3H, I_);

    cudaMemsetAsync(h0T, 0, (size_t)2 * H_ * B_ * sizeof(float));
    cudaMemsetAsync(h1T, 0, (size_t)2 * H_ * B_ * sizeof(float));
    cudaMemsetAsync(sy, 0, 1024 * sizeof(unsigned));

    gru_fused<<<GR, RT, FUS_SMEM_BYTES>>>(gi0, Whh0, bhh0, Wih1, bih1,
                                          Whh1, bhh1, Wfc, bfc, out, hid);
}

// round 17
// speedup vs baseline: 1.5391x; 1.0262x over previous
#include <cuda_runtime.h>
#include <cstdint>
#include <math.h>

#define B_   64
#define S_   1024
#define I_   256
#define H_   512
#define O_   512
#define G3H  1536

#define GR    148    // 96 GRU CTAs (barrier) + 52 self-paced FC rider CTAs
#define RT    256    // 8 warps -> 2 per SMSP
#define STEPS 1026   // GRU wavefront only; FC rider free-runs on release word

typedef unsigned long long u64;

// ---------------------------------------------------------------------------
// Device-global scratch
// ---------------------------------------------------------------------------
__device__ float    g_gi0  [(size_t)S_ * G3H * B_];   // gi0 [t][row][b]
__device__ float    g_gi1  [2 * G3H * B_];            // gi1 ring [slot][row][b]
__device__ float    g_h1sq [(size_t)S_ * H_ * B_];    // hseq1 transposed [t][j][b]
__device__ float    g_h0T  [2 * H_ * B_];             // h0 double buffer [slot][j][b]
__device__ float    g_h1T  [2 * H_ * B_];             // h1 double buffer [slot][j][b]
__device__ unsigned g_sync [1024];                    // leaves @ g*32 (0..11), root @800, release @832

// ---------------------------------------------------------------------------
// f32x2 + cp.async helpers
// ---------------------------------------------------------------------------
__device__ __forceinline__ u64 pk2(float x) {
    u64 r; asm("mov.b64 %0, {%1, %1};" : "=l"(r) : "r"(__float_as_uint(x))); return r;
}
__device__ __forceinline__ void fma2(u64& d, u64 a, u64 b) {
    asm("fma.rn.f32x2 %0, %1, %2, %0;" : "+l"(d) : "l"(a), "l"(b));
}
__device__ __forceinline__ float2 up2(u64 u) {
    unsigned lo, hi; asm("mov.b64 {%0, %1}, %2;" : "=r"(lo), "=r"(hi) : "l"(u));
    return make_float2(__uint_as_float(lo), __uint_as_float(hi));
}
__device__ __forceinline__ void cpa16(float* smem, const float* g) {
    unsigned s = (unsigned)__cvta_generic_to_shared(smem);
    asm volatile("cp.async.cg.shared.global [%0], [%1], 16;" :: "r"(s), "l"(g));
}
// Fast gates: ex2.approx + rcp.approx.
__device__ __forceinline__ float sigf(float x) {
    return __fdividef(1.f, 1.f + __expf(-x));
}
__device__ __forceinline__ float tanhf_(float x) {
    return __fdividef(2.f, 1.f + __expf(-2.f * x)) - 1.f;
}

// ---------------------------------------------------------------------------
// SGEMM + bias (verified DRAM-coalesced epilogue).
// A = x [B][S][I], M ordered m = t*64+b -> out gi[t][n][b].
// ---------------------------------------------------------------------------
template <int MODE>
__global__ void __launch_bounds__(256)
sgemm_bias(const float* __restrict__ A, const float* __restrict__ Bw,
           const float* __restrict__ bias, float* __restrict__ out,
           int M, int N, int K)
{
    __shared__ float As[16][132];
    __shared__ float Bs[16][68];

    const int tid = threadIdx.x;
    const int m0  = blockIdx.y * 128;
    const int n0  = blockIdx.x * 64;
    const int tx  = tid & 15;
    const int ty  = tid >> 4;

    const float* Bb = Bw + (size_t)n0 * K;

    u64 acc[4][4];
#pragma unroll
    for (int i = 0; i < 4; i++)
#pragma unroll
        for (int j = 0; j < 4; j++) acc[i][j] = 0ull;

    const int lr = tid >> 2;
    const int lk = (tid & 3) * 4;
    const int t0 = m0 >> 6;

    for (int kt = 0; kt < K; kt += 16) {
#pragma unroll
        for (int p = 0; p < 2; p++) {
            const int r = lr + p * 64;
            float4 v = *(const float4*)&A[((size_t)(r & 63) * S_ + t0 + (r >> 6)) * I_ + kt + lk];
            As[lk + 0][r] = v.x;
            As[lk + 1][r] = v.y;
            As[lk + 2][r] = v.z;
            As[lk + 3][r] = v.w;
        }
        {
            float4 v = *(const float4*)&Bb[(size_t)lr * K + kt + lk];
            Bs[lk + 0][lr] = v.x;
            Bs[lk + 1][lr] = v.y;
            Bs[lk + 2][lr] = v.z;
            Bs[lk + 3][lr] = v.w;
        }
        __syncthreads();

#pragma unroll
        for (int k = 0; k < 16; k++) {
            float4 bv = *(const float4*)&Bs[k][tx * 4];
            u64 bp0 = pk2(bv.x), bp1 = pk2(bv.y), bp2 = pk2(bv.z), bp3 = pk2(bv.w);
            ulonglong2 a01 = *(const ulonglong2*)&As[k][ty * 8];
            ulonglong2 a23 = *(const ulonglong2*)&As[k][ty * 8 + 4];
            u64 ap[4] = {a01.x, a01.y, a23.x, a23.y};
#pragma unroll
            for (int i = 0; i < 4; i++) {
                fma2(acc[i][0], ap[i], bp0);
                fma2(acc[i][1], ap[i], bp1);
                fma2(acc[i][2], ap[i], bp2);
                fma2(acc[i][3], ap[i], bp3);
            }
        }
        __syncthreads();
    }

    float bv[4];
    *(float4*)bv = *(const float4*)&bias[n0 + tx * 4];

    const int t  = t0 + (ty >> 3);
    const int b0 = (ty & 7) * 8;
#pragma unroll
    for (int j = 0; j < 4; j++) {
        const int n = n0 + tx * 4 + j;
        float2 p0 = up2(acc[0][j]), p1 = up2(acc[1][j]);
        float2 p2 = up2(acc[2][j]), p3 = up2(acc[3][j]);
        float4 w0, w1;
        w0.x = p0.x + bv[j]; w0.y = p0.y + bv[j];
        w0.z = p1.x + bv[j]; w0.w = p1.y + bv[j];
        w1.x = p2.x + bv[j]; w1.y = p2.y + bv[j];
        w1.z = p3.x + bv[j]; w1.w = p3.y + bv[j];
        float* q = out + ((size_t)t * G3H + n) * B_ + b0;
        *(float4*)&q[0] = w0;
        *(float4*)&q[4] = w1;
    }
}

// ---------------------------------------------------------------------------
// Fused two-layer GRU wavefront + SELF-PACED FC rider. 148 CTAs:
//  G0 (cta  0..31): h0[s]    = cell(h0[s-1], gi0[s])       s in [0,1024)
//  G1 (cta 32..63): gi1[s-1] = h0[s-1]@W_ih1^T + b          s in [1,1025)
//  G2 (cta 64..95): h1[s-2]  = cell(h1[s-3], gi1[s-2])      s in [2,1026)
//  G3 (cta 96..147): FC rider, NOT in the barrier — polls the release word
//     (release >= t+3 means h1sq[t] is final) and processes its tiles
//     t = (cta-96) + 52m at its own pace.
// Barrier: 96 GRU CTAs only (12 leaves x 8, root = 12).
// GRU mainloop: j-paired f32x2 (R15 verified), k-split 4, smem reduce.
// gru smem: hs 131072 @0 | Wp 98304 @131072
// G3  smem: htile 131072 @0 | wbuf 2x32768 @131072 | scratch 4096 @196608
// ---------------------------------------------------------------------------
#define FUS_SMEM_BYTES 229376

__device__ __forceinline__ void compute_phase(const float* __restrict__ hp,
                                              const u64* __restrict__ wp,
                                              u64* __restrict__ acc)
{
#pragma unroll 8
    for (int m = 0; m < 64; m++) {
        float4 hv = *(const float4*)(hp + m * 256);    // k advances by 4
        u64 hd0 = pk2(hv.x), hd1 = pk2(hv.y), hd2 = pk2(hv.z), hd3 = pk2(hv.w);
        const u64* wb = wp + m * 96;
        ulonglong2 wA = *(const ulonglong2*)(wb);
        ulonglong2 wB = *(const ulonglong2*)(wb + 2);
        ulonglong2 wC = *(const ulonglong2*)(wb + 4);
        fma2(acc[ 0], hd0, wA.x); fma2(acc[ 1], hd1, wA.x);
        fma2(acc[ 2], hd2, wA.x); fma2(acc[ 3], hd3, wA.x);
        fma2(acc[ 4], hd0, wA.y); fma2(acc[ 5], hd1, wA.y);
        fma2(acc[ 6], hd2, wA.y); fma2(acc[ 7], hd3, wA.y);
        fma2(acc[ 8], hd0, wB.x); fma2(acc[ 9], hd1, wB.x);
        fma2(acc[10], hd2, wB.x); fma2(acc[11], hd3, wB.x);
        fma2(acc[12], hd0, wB.y); fma2(acc[13], hd1, wB.y);
        fma2(acc[14], hd2, wB.y); fma2(acc[15], hd3, wB.y);
        fma2(acc[16], hd0, wC.x); fma2(acc[17], hd1, wC.x);
        fma2(acc[18], hd2, wC.x); fma2(acc[19], hd3, wC.x);
        fma2(acc[20], hd0, wC.y); fma2(acc[21], hd1, wC.y);
        fma2(acc[22], hd2, wC.y); fma2(acc[23], hd3, wC.y);
    }
}

__global__ void __launch_bounds__(RT, 1)
gru_fused(const float* __restrict__ gi0,
          const float* __restrict__ Whh0, const float* __restrict__ bhh0,
          const float* __restrict__ Wih1, const float* __restrict__ bih1,
          const float* __restrict__ Whh1, const float* __restrict__ bhh1,
          const float* __restrict__ Wfc,  const float* __restrict__ bfc,
          float* __restrict__ logits,     // [B][S][O]
          float* __restrict__ hid)        // [2][B][H]
{
    extern __shared__ float sm[];

    const int tid = threadIdx.x;
    const int cta = blockIdx.x;

    // ======================= G3: self-paced FC rider =======================
    if (cta >= 96) {
        float* hs      = sm;                 // 131072 B h tile
        float* wbuf    = sm + 32768;         // 2 x 32768 B Wfc double buffer
        float* scratch = sm + 49152;         // 4096 B transpose scratch

        const int nsub = tid >> 5;           // warp 0..7 -> 2 n each
        const int bp   = tid & 31;           // b-pair lane

        for (int tt = cta - 96; tt <= 1023; tt += 52) {
            // Wait for h1sq[tt] final: release >= tt+3 (all threads poll; acquire)
            {
                const unsigned tgt = (unsigned)(tt + 3);
                unsigned v;
                do {
                    asm volatile("ld.acquire.gpu.global.u32 %0, [%1];"
                                 : "=r"(v) : "l"(&g_sync[832]));
                    if (v < tgt) __nanosleep(512);
                } while (v < tgt);
            }
            asm volatile("fence.proxy.async;" ::: "memory");

            // Stage full h tile (128 KB) + Wfc cols [0,16) (32 KB), one group.
            const float* hsrcT = g_h1sq + (size_t)tt * (H_ * B_);
#pragma unroll
            for (int u = 0; u < 32; u++)
                cpa16(hs + (tid + u * RT) * 4, hsrcT + (tid + u * RT) * 4);
#pragma unroll
            for (int u = 0; u < 8; u++)
                cpa16(wbuf + (tid + u * RT) * 4, Wfc + (tid + u * RT) * 4);
            asm volatile("cp.async.commit_group;");

            for (int q = 0; q < 32; q++) {
                const int nc0 = q * 16;
                if (q + 1 < 32) {
                    const float* wsrc = Wfc + (size_t)(nc0 + 16) * 512;
                    float* wd = wbuf + ((q + 1) & 1) * 8192;
#pragma unroll
                    for (int u = 0; u < 8; u++)
                        cpa16(wd + (tid + u * RT) * 4, wsrc + (tid + u * RT) * 4);
                    asm volatile("cp.async.commit_group;");
                    asm volatile("cp.async.wait_group 1;");
                } else {
                    asm volatile("cp.async.wait_group 0;");
                }
                __syncthreads();

                const float* w0p = wbuf + (q & 1) * 8192 + (nsub * 2) * 512;
                const float* w1p = w0p + 512;
                u64 a0 = 0ull, a1 = 0ull;
#pragma unroll 4
                for (int k = 0; k < 512; k += 4) {
                    float4 w0 = *(const float4*)&w0p[k];
                    float4 w1 = *(const float4*)&w1p[k];
                    u64 h0 = *(const u64*)&hs[(k + 0) * 64 + bp * 2];
                    u64 h1 = *(const u64*)&hs[(k + 1) * 64 + bp * 2];
                    u64 h2 = *(const u64*)&hs[(k + 2) * 64 + bp * 2];
                    u64 h3 = *(const u64*)&hs[(k + 3) * 64 + bp * 2];
                    fma2(a0, h0, pk2(w0.x)); fma2(a1, h0, pk2(w1.x));
                    fma2(a0, h1, pk2(w0.y)); fma2(a1, h1, pk2(w1.y));
                    fma2(a0, h2, pk2(w0.z)); fma2(a1, h2, pk2(w1.z));
                    fma2(a0, h3, pk2(w0.w)); fma2(a1, h3, pk2(w1.w));
                }
                const int n0 = nc0 + nsub * 2;
                float bb0 = bfc[n0], bb1 = bfc[n0 + 1];
                float2 v0 = up2(a0), v1 = up2(a1);
                scratch[(nsub * 2 + 0) * 64 + bp * 2]     = v0.x + bb0;
                scratch[(nsub * 2 + 0) * 64 + bp * 2 + 1] = v0.y + bb0;
                scratch[(nsub * 2 + 1) * 64 + bp * 2]     = v1.x + bb1;
                scratch[(nsub * 2 + 1) * 64 + bp * 2 + 1] = v1.y + bb1;
                __syncthreads();

                {
                    const int b  = tid >> 2;
                    const int nq = tid & 3;
                    float4 o;
                    o.x = scratch[(nq * 4 + 0) * 64 + b];
                    o.y = scratch[(nq * 4 + 1) * 64 + b];
                    o.z = scratch[(nq * 4 + 2) * 64 + b];
                    o.w = scratch[(nq * 4 + 3) * 64 + b];
                    *(float4*)&logits[((size_t)b * S_ + tt) * O_ + nc0 + nq * 4] = o;
                }
                __syncthreads();
            }
        }
        return;
    }

    // =========================== GRU wavefront =============================
    float* hs = sm;                                  // 131072 B (full h state)
    u64*   Wp = (u64*)((char*)sm + 131072);          // 98304 B weights

    const int grp   = cta >> 5;
    const int lc    = cta & 31;
    const int jbase = lc * 16;

    const float* Wsrc = (grp == 0) ? Whh0 : (grp == 1) ? Wih1 : Whh1;

    // J-paired weight preload
    for (int i = tid; i < 12288; i += RT) {
        int w6   = i % 6;
        int rest = i / 6;
        int jq   = rest & 3;
        int k    = rest >> 2;
        int p = w6 / 3, g = w6 % 3;
        int j0 = jbase + jq * 4 + p * 2;
        float w0 = Wsrc[(size_t)(g * 512 + j0)     * 512 + k];
        float w1 = Wsrc[(size_t)(g * 512 + j0 + 1) * 512 + k];
        Wp[i] = (u64)__float_as_uint(w0) | ((u64)__float_as_uint(w1) << 32);
    }

    // Compute mapping
    const int ks = tid >> 6;
    const int jq = (tid >> 4) & 3;
    const int bs = tid & 15;
    const int bA = bs * 4;

    // Finalize mapping
    const int fjl = tid >> 4;
    const int fbs = tid & 15;
    const int fbA = fbs * 4;
    const int fj  = jbase + fjl;
    const int fq  = fjl >> 2;
    const int fp  = (fjl >> 1) & 1;
    const int fe  = fjl & 1;

    float br = 0.f, bz = 0.f, bn = 0.f;
    if (grp == 0) { br = bhh0[fj]; bz = bhh0[512 + fj]; bn = bhh0[1024 + fj]; }
    if (grp == 1) { br = bih1[fj]; bz = bih1[512 + fj]; bn = bih1[1024 + fj]; }
    if (grp == 2) { br = bhh1[fj]; bz = bhh1[512 + fj]; bn = bhh1[1024 + fj]; }

    __syncthreads();

    for (int s = 0; s < STEPS; s++) {
        const bool active = (grp == 0) ? (s < 1024)
                          : (grp == 1) ? (s >= 1 && s < 1025)
                                       : (s >= 2);
        if (active) {
            const float* hsrc = ((grp == 2) ? g_h1T : g_h0T)
                              + (((grp == 2 ? s - 2 : s) + 1) & 1) * (H_ * B_);

            // Issue all 8 chunk groups (16 KB each) of the full h state.
#pragma unroll
            for (int c = 0; c < 8; c++) {
                const float* s4 = hsrc + c * 4096;
                float*       d4 = hs   + c * 4096;
#pragma unroll
                for (int u = 0; u < 4; u++)
                    cpa16(d4 + (tid + u * RT) * 4, s4 + (tid + u * RT) * 4);
                asm volatile("cp.async.commit_group;");
            }

            float GIR[4], GIZ[4], GIN[4], hold[4];
            if (grp != 1) {
                const float* p = (grp == 0)
                    ? gi0   + (size_t)s * (G3H * 64)
                    : g_gi1 + (size_t)(s & 1) * (G3H * 64);
                *(float4*)&GIR[0]  = *(const float4*)&p[(size_t)fj          * 64 + fbA];
                *(float4*)&GIZ[0]  = *(const float4*)&p[(size_t)(512 + fj)  * 64 + fbA];
                *(float4*)&GIN[0]  = *(const float4*)&p[(size_t)(1024 + fj) * 64 + fbA];
                *(float4*)&hold[0] = *(const float4*)&hsrc[fj * 64 + fbA];
            }

            u64 acc[24];
#pragma unroll
            for (int i = 0; i < 24; i++) acc[i] = 0ull;

            asm volatile("cp.async.wait_group 4;");
            __syncthreads();
            compute_phase(hs + (size_t)ks * 64 + bA,
                          Wp + ((size_t)ks * 4 + jq) * 6, acc);

            asm volatile("cp.async.wait_group 0;");
            __syncthreads();
            compute_phase(hs + (size_t)(256 + ks) * 64 + bA,
                          Wp + ((size_t)(256 + ks) * 4 + jq) * 6, acc);

            // K-split reduce via padded smem scratch (dead h region)
            u64* P = (u64*)hs;
            {
                u64* pp = P + (size_t)tid * 26;
#pragma unroll
                for (int q2 = 0; q2 < 12; q2++)
                    *(ulonglong2*)(pp + q2 * 2) =
                        make_ulonglong2(acc[q2 * 2], acc[q2 * 2 + 1]);
            }
            __syncthreads();

            float Rg[4], Zg[4], Ng[4];
#pragma unroll
            for (int g = 0; g < 3; g++) {
                float Sv[4] = {0.f, 0.f, 0.f, 0.f};
#pragma unroll
                for (int kss = 0; kss < 4; kss++) {
                    const u64* qb = P + (size_t)(kss * 64 + fq * 16 + fbs) * 26
                                      + (fp * 3 + g) * 4;
                    ulonglong2 u01 = *(const ulonglong2*)qb;
                    ulonglong2 u23 = *(const ulonglong2*)(qb + 2);
                    float2 f0 = up2(u01.x), f1 = up2(u01.y);
                    float2 f2 = up2(u23.x), f3 = up2(u23.y);
                    Sv[0] += fe ? f0.y : f0.x;
                    Sv[1] += fe ? f1.y : f1.x;
                    Sv[2] += fe ? f2.y : f2.x;
                    Sv[3] += fe ? f3.y : f3.x;
                }
                if (g == 0)      { Rg[0]=Sv[0]; Rg[1]=Sv[1]; Rg[2]=Sv[2]; Rg[3]=Sv[3]; }
                else if (g == 1) { Zg[0]=Sv[0]; Zg[1]=Sv[1]; Zg[2]=Sv[2]; Zg[3]=Sv[3]; }
                else             { Ng[0]=Sv[0]; Ng[1]=Sv[1]; Ng[2]=Sv[2]; Ng[3]=Sv[3]; }
            }

            if (grp == 1) {
                float* q = g_gi1 + (size_t)((s - 1) & 1) * (G3H * 64);
                float o[4];
#pragma unroll
                for (int i = 0; i < 4; i++) o[i] = Rg[i] + br;
                *(float4*)&q[(size_t)fj * 64 + fbA] = *(float4*)&o[0];
#pragma unroll
                for (int i = 0; i < 4; i++) o[i] = Zg[i] + bz;
                *(float4*)&q[(size_t)(512 + fj) * 64 + fbA] = *(float4*)&o[0];
#pragma unroll
                for (int i = 0; i < 4; i++) o[i] = Ng[i] + bn;
                *(float4*)&q[(size_t)(1024 + fj) * 64 + fbA] = *(float4*)&o[0];
            } else {
                float hn[4];
#pragma unroll
                for (int i = 0; i < 4; i++) {
                    float r_ = sigf(GIR[i] + Rg[i] + br);
                    float z_ = sigf(GIZ[i] + Zg[i] + bz);
                    float n_ = tanhf_(GIN[i] + r_ * (Ng[i] + bn));
                    hn[i] = (1.f - z_) * n_ + z_ * hold[i];
                }

                const int tau = (grp == 2) ? s - 2 : s;
                float* hdT = ((grp == 2) ? g_h1T : g_h0T) + (tau & 1) * (H_ * B_);
                *(float4*)&hdT[fj * 64 + fbA] = *(float4*)&hn[0];

                if (grp == 2) {
                    float* hq = g_h1sq + (size_t)tau * (H_ * B_);
                    *(float4*)&hq[fj * 64 + fbA] = *(float4*)&hn[0];
                }
                if (tau == S_ - 1) {
                    float* hd = hid + (grp == 2 ? B_ * H_ : 0);
#pragma unroll
                    for (int i = 0; i < 4; i++)
                        hd[(size_t)(fbA + i) * H_ + fj] = hn[i];
                }
            }
        }

        // ---- two-level grid barrier over the 96 GRU CTAs (12 leaves x 8) ----
        __syncthreads();
        if (tid == 0) {
            __threadfence();
            unsigned go = atomicAdd(&g_sync[(cta >> 3) * 32], 1u);
            if (go == (unsigned)(s + 1) * 8 - 1) {
                unsigned ro = atomicAdd(&g_sync[800], 1u);
                if (ro == (unsigned)(s + 1) * 12 - 1) {
                    __threadfence();
                    *((volatile unsigned*)&g_sync[832]) = (unsigned)(s + 1);
                }
            }
            while (*((volatile unsigned*)&g_sync[832]) < (unsigned)(s + 1)) { }
            __threadfence();
        }
        __syncthreads();
    }
}

// ---------------------------------------------------------------------------
// Launch
// ---------------------------------------------------------------------------
extern "C" void kernel_launch(void* const* d_in, const int* in_sizes, int n_in,
                              void* d_out, int out_size)
{
    const float* x    = (const float*)d_in[0];
    const float* Wih0 = (const float*)d_in[1];
    const float* Whh0 = (const float*)d_in[2];
    const float* bih0 = (const float*)d_in[3];
    const float* bhh0 = (const float*)d_in[4];
    const float* Wih1 = (const float*)d_in[5];
    const float* Whh1 = (const float*)d_in[6];
    const float* bih1 = (const float*)d_in[7];
    const float* bhh1 = (const float*)d_in[8];
    const float* Wfc  = (const float*)d_in[9];
    const float* bfc  = (const float*)d_in[10];

    float* out = (float*)d_out;                    // logits [B][S][O]
    float* hid = out + (size_t)B_ * S_ * O_;       // hidden [2][B][H]

    float *gi0, *h0T, *h1T;
    unsigned* sy;
    cudaGetSymbolAddress((void**)&gi0,  g_gi0);
    cudaGetSymbolAddress((void**)&h0T,  g_h0T);
    cudaGetSymbolAddress((void**)&h1T,  g_h1T);
    cudaGetSymbolAddress((void**)&sy,   g_sync);

    cudaFuncSetAttribute(gru_fused, cudaFuncAttributeMaxDynamicSharedMemorySize,
                         FUS_SMEM_BYTES);

    const int M = B_ * S_;
    dim3 blk(256);
    dim3 gGI(G3H / 64, M / 128);   // 24 x 512

    // gi0 = x @ W_ih0^T + b_ih0   -> [t][row][b]
    sgemm_bias<0><<<gGI, blk>>>(x, Wih0, bih0, gi0, M, G3H, I_);

    cudaMemsetAsync(h0T, 0, (size_t)2 * H_ * B_ * sizeof(float));
    cudaMemsetAsync(h1T, 0, (size_t)2 * H_ * B_ * sizeof(float));
    cudaMemsetAsync(sy, 0, 1024 * sizeof(unsigned));

    gru_fused<<<GR, RT, FUS_SMEM_BYTES>>>(gi0, Whh0, bhh0, Wih1, bih1,
                                          Whh1, bhh1, Wfc, bfc, out, hid);
}